// round 10
// baseline (speedup 1.0000x reference)
#include <cuda_runtime.h>
#include <cuda_bf16.h>
#include <math.h>
#include <stdint.h>

// Problem constants (fixed by setup_inputs)
constexpr int B  = 4;
constexpr int H  = 256;
constexpr int W  = 256;
constexpr int C  = 256;
constexpr int K  = 1024;
constexpr int NP = 25;    // 5x5 window
constexpr int MAXPTS = B * K;   // 4096

// Mathematical reduction of the reference (validated R5-R9: rel_err 1.49e-8):
//   Attention messages are broadcast-constant along the window axis n; every
//   consumer applies a softmax over n (shift-invariant) -> both layers and
//   Wq/Wk/Wv/Wo cancel exactly.
//   Output = pos + softmax_n(corr[n]) . offsets, with
//     corr[n] = sum_{g in [256n,256n+256)} win[g] * s[g & 255],
//   win[g] (g = ch*25 + p) the channel-scrambled window gather and
//   s[ch] = win_row12[ch] (window center).
//
// R9 lesson: DRAM bytes are already minimal (L2 dedups to unique footprint);
// achieved BW (~3.8 TB/s) is invariant to SM-side structure -> test whether
// it is DRAM row-locality bound by spatially sorting the points so that
// concurrently-resident CTAs gather from adjacent memory.

__device__ int g_perm[MAXPTS];

// ---------- Spatial counting sort: one block, 1024 threads ----------
// key = (batch << 10) | ((r>>3) << 5) | (c>>3)   in [0, 4096)
__global__ __launch_bounds__(1024)
void sort_kernel(const float* __restrict__ pos, int n) {
    __shared__ int cnt[4096];     // 16 KB
    __shared__ int ssum[1024];
    const int t = threadIdx.x;

    #pragma unroll
    for (int i = t; i < 4096; i += 1024) cnt[i] = 0;
    __syncthreads();

    int keys[4], pts[4], np = 0;
    for (int pt = t; pt < n && np < 4; pt += 1024) {
        const float pr = pos[2 * pt + 0];
        const float pc = pos[2 * pt + 1];
        const int r = (int)pr, c = (int)pc;       // in [0, 255]
        const int b = pt >> 10;                   // K = 1024
        const int key = (b << 10) | ((r >> 3) << 5) | (c >> 3);
        keys[np] = key; pts[np] = pt; ++np;
        atomicAdd(&cnt[key], 1);
    }
    __syncthreads();

    // Blocked exclusive scan over the 4096 counters (4 per thread).
    const int c0 = cnt[4 * t + 0], c1 = cnt[4 * t + 1];
    const int c2 = cnt[4 * t + 2], c3 = cnt[4 * t + 3];
    const int s  = c0 + c1 + c2 + c3;
    ssum[t] = s;
    __syncthreads();
    #pragma unroll
    for (int d = 1; d < 1024; d <<= 1) {
        const int v = (t >= d) ? ssum[t - d] : 0;
        __syncthreads();
        ssum[t] += v;
        __syncthreads();
    }
    const int excl = ssum[t] - s;
    cnt[4 * t + 0] = excl;
    cnt[4 * t + 1] = excl + c0;
    cnt[4 * t + 2] = excl + c0 + c1;
    cnt[4 * t + 3] = excl + c0 + c1 + c2;
    __syncthreads();

    // Scatter. Within-bucket order may race, but every point's downstream
    // computation and output slot depend only on the point itself, so the
    // final output is bitwise deterministic.
    for (int i = 0; i < np; ++i)
        g_perm[atomicAdd(&cnt[keys[i]], 1)] = pts[i];
}

// ---------- Main kernel: identical to R8 (best: 21.2us) + perm ----------
__device__ __forceinline__ uint32_t smem_u32(const void* p) {
    return (uint32_t)__cvta_generic_to_shared(p);
}

__global__ __launch_bounds__(256)
void fine_match_kernel(const float* __restrict__ T,
                       const float* __restrict__ pos,
                       float* __restrict__ out) {
    __shared__ __align__(16) float win[NP][C];   // 25.6 KB
    __shared__ float part0[256];
    __shared__ float part1[256];
    __shared__ float corr_sm[NP];
    __shared__ __align__(8) uint64_t mbar;

    const int bk = g_perm[blockIdx.x];   // spatially sorted point index
    const int b  = bk >> 10;             // K = 1024
    const int t  = threadIdx.x;

    const float pr = pos[bk * 2 + 0];
    const float pc = pos[bk * 2 + 1];
    const int r = (int)pr;               // astype(int32) truncation; pos >= 0
    const int c = (int)pc;

    const uint32_t mbar_a = smem_u32(&mbar);
    if (t == 0) {
        asm volatile("mbarrier.init.shared.b64 [%0], 1;" :: "r"(mbar_a) : "memory");
    }
    __syncthreads();

    // ---- TMA gather: warp 0 issues 25 x 1KB bulk copies (valid rows only) ----
    const char* __restrict__ Tb = (const char*)(T + (size_t)b * H * W * C);
    if (t < 32) {
        const int p  = t;
        const int rr = r - 2 + p / 5;
        const int cc = c - 2 + p % 5;
        const bool valid = (t < NP) & (rr >= 0) & (rr < H) & (cc >= 0) & (cc < W);
        const unsigned vmask = __ballot_sync(0xffffffffu, valid);
        if (t == 0) {
            const uint32_t txbytes = (uint32_t)__popc(vmask) * (C * 4);
            asm volatile("mbarrier.arrive.expect_tx.shared.b64 _, [%0], %1;"
                         :: "r"(mbar_a), "r"(txbytes) : "memory");
        }
        __syncwarp();
        if (valid) {
            const char* src = Tb + ((size_t)rr * W + cc) * (C * 4);
            asm volatile(
                "cp.async.bulk.shared::cta.global.mbarrier::complete_tx::bytes "
                "[%0], [%1], %2, [%3];"
                :: "r"(smem_u32(&win[p][0])), "l"(src), "r"(C * 4), "r"(mbar_a)
                : "memory");
        }
    }

    // ---- Zero out-of-range rows (border points only) ----
    if (r < 2 || r > H - 3 || c < 2 || c > W - 3) {
        #pragma unroll
        for (int p = 0; p < NP; ++p) {
            const int rr = r - 2 + p / 5;
            const int cc = c - 2 + p % 5;
            if (rr < 0 || rr >= H || cc < 0 || cc >= W)
                win[p][t] = 0.0f;
        }
    }
    __syncthreads();

    // ---- Wait for the gather (acquire orders smem reads after TMA writes) ----
    {
        uint32_t done;
        do {
            asm volatile(
                "{\n\t.reg .pred p;\n\t"
                "mbarrier.try_wait.parity.acquire.cta.shared::cta.b64 p, [%1], %2, 0x989680;\n\t"
                "selp.b32 %0, 1, 0, p;\n\t}"
                : "=r"(done) : "r"(mbar_a), "r"(0u) : "memory");
        } while (!done);
    }

    // ---- Per-thread partial dot (thread t owns channel t of all rows) ----
    const int g0 = t * NP;
    const int m0 = g0 & (C - 1);
    const int ps = C - m0;
    float a0 = 0.0f, a1 = 0.0f;
    #pragma unroll
    for (int p = 0; p < NP; ++p) {
        // win[p][t]: lane-consecutive; win[12][.]: stride 25 -> conflict-free
        const int sidx = (p < ps) ? (m0 + p) : (m0 + p - C);
        const float f = win[p][t] * win[12][sidx];
        if (p < ps) a0 += f; else a1 += f;
    }
    part0[t] = a0;
    part1[t] = a1;
    __syncthreads();

    // ---- Deterministic segmented reduction over the 25 bins ----
    if (t < NP) {
        const int n    = t;
        const int t_lo = (256 * n) / 25;
        const int t_hi = min(255, (256 * n + 255) / 25);
        float acc = 0.0f;
        for (int tt = t_lo; tt <= t_hi; ++tt)
            acc += (((tt * NP) >> 8) == n) ? part0[tt] : part1[tt];
        corr_sm[n] = acc;
    }
    __syncwarp();

    // ---- Softmax over 25 logits + expectation over offsets (warp 0) ----
    if (t < 32) {
        const bool valid = (t < NP);
        float lv = valid ? corr_sm[t] : -INFINITY;
        float m = lv;
        #pragma unroll
        for (int o = 16; o; o >>= 1)
            m = fmaxf(m, __shfl_xor_sync(0xffffffffu, m, o));
        float e = valid ? expf(lv - m) : 0.0f;
        float sum = e;
        #pragma unroll
        for (int o = 16; o; o >>= 1)
            sum += __shfl_xor_sync(0xffffffffu, sum, o);

        // off1d = linspace(-3, 2, 5) = -3 + 1.25*idx (faithful -w//2 = -3)
        float ox = 0.0f, oy = 0.0f;
        if (valid) {
            ox = -3.0f + 1.25f * (float)(t / 5);
            oy = -3.0f + 1.25f * (float)(t % 5);
        }
        float dx = e * ox;
        float dy = e * oy;
        #pragma unroll
        for (int o = 16; o; o >>= 1) {
            dx += __shfl_xor_sync(0xffffffffu, dx, o);
            dy += __shfl_xor_sync(0xffffffffu, dy, o);
        }
        if (t == 0) {
            const float inv = 1.0f / sum;
            out[bk * 2 + 0] = pr + dx * inv;
            out[bk * 2 + 1] = pc + dy * inv;
        }
    }
}

extern "C" void kernel_launch(void* const* d_in, const int* in_sizes, int n_in,
                              void* d_out, int out_size) {
    // metadata order: source_features, target_features, coarse_positions,
    //                 Wq, Wk, Wv, Wo.
    // source_features and all weight matrices are provably unused (softmax
    // shift-invariance eliminates the attention layers entirely).
    const float* target = (const float*)d_in[1];
    const float* pos    = (const float*)d_in[2];
    float* out          = (float*)d_out;

    const int n_points = in_sizes[2] / 2;   // 4096 for the pinned shape

    sort_kernel<<<1, 1024>>>(pos, n_points);
    fine_match_kernel<<<n_points, 256>>>(target, pos, out);
}

// round 15
// speedup vs baseline: 1.1792x; 1.1792x over previous
#include <cuda_runtime.h>
#include <cuda_bf16.h>
#include <math.h>
#include <stdint.h>

// Problem constants (fixed by setup_inputs)
constexpr int B  = 4;
constexpr int H  = 256;
constexpr int W  = 256;
constexpr int C  = 256;
constexpr int K  = 1024;
constexpr int NP = 25;    // 5x5 window
constexpr int NT = 17;    // rows 0..16 gathered via TMA (includes center row 12)
constexpr int NL = NP - NT;  // rows 17..24 gathered via per-thread LDG

// Mathematical reduction of the reference (validated R5-R10: rel_err 1.49e-8):
//   Attention messages are broadcast-constant along the window axis n; every
//   consumer applies a softmax over n (shift-invariant) -> both layers and
//   Wq/Wk/Wv/Wo cancel exactly.
//   Output = pos + softmax_n(corr[n]) . offsets, with
//     corr[n] = sum_{g in [256n,256n+256)} win[g] * s[g & 255],
//   win[g] (g = ch*25 + p) the channel-scrambled window gather and
//   s[ch] = win_row12[ch] (window center).
//
// R10 lesson: achieved BW (~3.8 TB/s) is invariant to SM-side structure AND
// to DRAM-row locality -> hypothesis: per-SM outstanding-request cap on a
// single memory path (Little's law: 3.8TB/s x ~300ns ~ 64 lines/SM).
// This version drives TWO independent paths concurrently: TMA bulk copies
// (rows 0..16) + per-thread register LDGs (rows 17..24).

__device__ __forceinline__ uint32_t smem_u32(const void* p) {
    return (uint32_t)__cvta_generic_to_shared(p);
}

__global__ __launch_bounds__(256)
void fine_match_kernel(const float* __restrict__ T,
                       const float* __restrict__ pos,
                       float* __restrict__ out) {
    __shared__ __align__(16) float win[NT][C];   // 17.4 KB
    __shared__ float part0[256];
    __shared__ float part1[256];
    __shared__ float corr_sm[NP];
    __shared__ __align__(8) uint64_t mbar;

    const int bk = blockIdx.x;           // 0 .. B*K-1
    const int b  = bk >> 10;             // K = 1024
    const int t  = threadIdx.x;

    const float pr = pos[bk * 2 + 0];
    const float pc = pos[bk * 2 + 1];
    const int r = (int)pr;               // astype(int32) truncation; pos >= 0
    const int c = (int)pc;

    const uint32_t mbar_a = smem_u32(&mbar);
    if (t == 0) {
        asm volatile("mbarrier.init.shared.b64 [%0], 1;" :: "r"(mbar_a) : "memory");
    }
    __syncthreads();

    const float* __restrict__ Tb = T + (size_t)b * H * W * C;

    // ---- Path 1: TMA gather of rows 0..16 (warp 0; valid rows only) ----
    if (t < 32) {
        const int p  = t;
        const int rr = r - 2 + p / 5;
        const int cc = c - 2 + p % 5;
        const bool valid = (t < NT) & (rr >= 0) & (rr < H) & (cc >= 0) & (cc < W);
        const unsigned vmask = __ballot_sync(0xffffffffu, valid);
        if (t == 0) {
            const uint32_t txbytes = (uint32_t)__popc(vmask) * (C * 4);
            asm volatile("mbarrier.arrive.expect_tx.shared.b64 _, [%0], %1;"
                         :: "r"(mbar_a), "r"(txbytes) : "memory");
        }
        __syncwarp();
        if (valid) {
            const char* src = (const char*)(Tb + ((size_t)rr * W + cc) * C);
            asm volatile(
                "cp.async.bulk.shared::cta.global.mbarrier::complete_tx::bytes "
                "[%0], [%1], %2, [%3];"
                :: "r"(smem_u32(&win[p][0])), "l"(src), "r"(C * 4), "r"(mbar_a)
                : "memory");
        }
    }

    // ---- Path 2: per-thread LDG of rows 17..24, channel t, into registers ----
    // 8 independent coalesced loads per thread -> front-batched, high MLP on
    // the LSU/L1tex path, concurrent with the TMA transfers above.
    float v[NL];
    #pragma unroll
    for (int q = 0; q < NL; ++q) {
        const int p  = NT + q;
        const int rr = r - 2 + p / 5;
        const int cc = c - 2 + p % 5;
        const bool ok = (rr >= 0) & (rr < H) & (cc >= 0) & (cc < W);
        v[q] = ok ? Tb[(size_t)(rr * W + cc) * C + t] : 0.0f;
    }

    // ---- Zero out-of-range TMA rows (border points only). Each thread
    //      zeroes exactly the элементы it reads (win[p][t]); row 12 (center)
    //      is always in range, so the cross-thread s-reads are unaffected. ----
    if (r < 2 || r > H - 3 || c < 2 || c > W - 3) {
        #pragma unroll
        for (int p = 0; p < NT; ++p) {
            const int rr = r - 2 + p / 5;
            const int cc = c - 2 + p % 5;
            if (rr < 0 || rr >= H || cc < 0 || cc >= W)
                win[p][t] = 0.0f;
        }
    }

    // ---- Wait for TMA (acquire orders smem reads after TMA writes) ----
    {
        uint32_t done;
        do {
            asm volatile(
                "{\n\t.reg .pred p;\n\t"
                "mbarrier.try_wait.parity.acquire.cta.shared::cta.b64 p, [%1], %2, 0x989680;\n\t"
                "selp.b32 %0, 1, 0, p;\n\t}"
                : "=r"(done) : "r"(mbar_a), "r"(0u) : "memory");
        } while (!done);
    }

    // ---- Per-thread partial dot (thread t owns channel t of all rows) ----
    // g = t*25 + p; s[g&255] = win[12][.]; bin n = g>>8 spans <= 2.
    // Identical p-order fmaf chain as R8 -> bitwise-identical results.
    const int g0 = t * NP;
    const int m0 = g0 & (C - 1);
    const int ps = C - m0;
    float a0 = 0.0f, a1 = 0.0f;
    #pragma unroll
    for (int p = 0; p < NP; ++p) {
        const int sidx = (p < ps) ? (m0 + p) : (m0 + p - C);
        const float wv = (p < NT) ? win[p][t] : v[p - NT];
        const float f = wv * win[12][sidx];
        if (p < ps) a0 += f; else a1 += f;
    }
    part0[t] = a0;
    part1[t] = a1;
    __syncthreads();

    // ---- Deterministic segmented reduction over the 25 bins ----
    if (t < NP) {
        const int n    = t;
        const int t_lo = (256 * n) / 25;
        const int t_hi = min(255, (256 * n + 255) / 25);
        float acc = 0.0f;
        for (int tt = t_lo; tt <= t_hi; ++tt)
            acc += (((tt * NP) >> 8) == n) ? part0[tt] : part1[tt];
        corr_sm[n] = acc;
    }
    __syncwarp();

    // ---- Softmax over 25 logits + expectation over offsets (warp 0) ----
    if (t < 32) {
        const bool valid = (t < NP);
        float lv = valid ? corr_sm[t] : -INFINITY;
        float m = lv;
        #pragma unroll
        for (int o = 16; o; o >>= 1)
            m = fmaxf(m, __shfl_xor_sync(0xffffffffu, m, o));
        float e = valid ? expf(lv - m) : 0.0f;
        float sum = e;
        #pragma unroll
        for (int o = 16; o; o >>= 1)
            sum += __shfl_xor_sync(0xffffffffu, sum, o);

        // off1d = linspace(-3, 2, 5) = -3 + 1.25*idx (faithful -w//2 = -3)
        float ox = 0.0f, oy = 0.0f;
        if (valid) {
            ox = -3.0f + 1.25f * (float)(t / 5);
            oy = -3.0f + 1.25f * (float)(t % 5);
        }
        float dx = e * ox;
        float dy = e * oy;
        #pragma unroll
        for (int o = 16; o; o >>= 1) {
            dx += __shfl_xor_sync(0xffffffffu, dx, o);
            dy += __shfl_xor_sync(0xffffffffu, dy, o);
        }
        if (t == 0) {
            const float inv = 1.0f / sum;
            out[bk * 2 + 0] = pr + dx * inv;
            out[bk * 2 + 1] = pc + dy * inv;
        }
    }
}

extern "C" void kernel_launch(void* const* d_in, const int* in_sizes, int n_in,
                              void* d_out, int out_size) {
    // metadata order: source_features, target_features, coarse_positions,
    //                 Wq, Wk, Wv, Wo.
    // source_features and all weight matrices are provably unused (softmax
    // shift-invariance eliminates the attention layers entirely).
    const float* target = (const float*)d_in[1];
    const float* pos    = (const float*)d_in[2];
    float* out          = (float*)d_out;

    const int n_points = in_sizes[2] / 2;   // 4096 for the pinned shape
    fine_match_kernel<<<n_points, 256>>>(target, pos, out);
}